// round 4
// baseline (speedup 1.0000x reference)
#include <cuda_runtime.h>
#include <math.h>

// B=16, S=128, N=64, E=DK=H=128, L=32

// -------- device scratch --------
__device__ float g_Xg[2*16*128*512];   // X@Wcx+bc, scan order
__device__ float g_Xl[2*16*128*128];   // X@Wlx+bl
__device__ float g_Wg[2*16*64*384];    // Xw@Wwx+bw
__device__ float g_feats[16*128*256];
__device__ float g_logits[16*128*32];
__device__ float g_res[16];

__device__ __forceinline__ float sigm(float x) { return 1.f / (1.f + expf(-x)); }

__device__ __forceinline__ unsigned smem_u32(const void* p) {
    unsigned a;
    asm("{ .reg .u64 t; cvta.to.shared.u64 t, %1; cvt.u32.u64 %0, t; }" : "=r"(a) : "l"(p));
    return a;
}
__device__ __forceinline__ void st_peer_f32(unsigned a, int p, float v) {
    unsigned r;
    asm volatile("mapa.shared::cluster.u32 %0, %1, %2;" : "=r"(r) : "r"(a), "r"(p));
    asm volatile("st.shared::cluster.f32 [%0], %1;" :: "r"(r), "f"(v) : "memory");
}
__device__ __forceinline__ void mbar_init(unsigned a, unsigned c) {
    asm volatile("mbarrier.init.shared.b64 [%0], %1;" :: "r"(a), "r"(c) : "memory");
}
__device__ __forceinline__ void mbar_arrive_self(unsigned a) {
    asm volatile("mbarrier.arrive.release.cluster.shared::cta.b64 _, [%0];" :: "r"(a) : "memory");
}
__device__ __forceinline__ void mbar_arrive_peer(unsigned a, int p) {
    unsigned r;
    asm volatile("mapa.shared::cluster.u32 %0, %1, %2;" : "=r"(r) : "r"(a), "r"(p));
    asm volatile("mbarrier.arrive.release.cluster.shared::cluster.b64 _, [%0];" :: "r"(r) : "memory");
}
__device__ __forceinline__ void mbar_wait(unsigned a, unsigned parity) {
    asm volatile("{\n\t.reg .pred P;\n"
        "WL%=:\n\tmbarrier.try_wait.parity.acquire.cluster.shared::cta.b64 P, [%0], %1, 0x989680;\n"
        "\t@P bra WD%=;\n\tbra WL%=;\nWD%=:\n\t}" :: "r"(a), "r"(parity) : "memory");
}
__device__ __forceinline__ void cluster_sync_() {
    asm volatile("barrier.cluster.arrive.aligned;" ::: "memory");
    asm volatile("barrier.cluster.wait.aligned;" ::: "memory");
}

// ---------------- precompute GEMMs with embedding gather ----------------
__global__ void gemm_gather_kernel(int mode,
    const int* __restrict__ char_ids, const int* __restrict__ kb_ids,
    const float* __restrict__ char_emb, const float* __restrict__ kb_emb,
    const float* __restrict__ Wf, const float* __restrict__ Wr,
    const float* __restrict__ bf, const float* __restrict__ br,
    int C, int rows_per_dir)
{
    __shared__ float As[64 * 128];
    __shared__ float Wsm[32 * 64];
    __shared__ int ids[64];
    int tid = threadIdx.x;
    int c0 = blockIdx.x * 64;
    int r0 = blockIdx.y * 64;
    int dir = (r0 >= rows_per_dir) ? 1 : 0;

    float* out = (mode == 0) ? g_Xg : (mode == 1) ? g_Xl : g_Wg;
    const float* emb = (mode == 2) ? kb_emb : char_emb;

    if (tid < 64) {
        int r = r0 + tid;
        int id;
        if (mode < 2) {
            int t = r & 127, b = (r >> 7) & 15;
            int pos = dir ? (127 - t) : t;
            id = char_ids[b * 128 + pos];
        } else {
            int w = r & 63, b = (r >> 6) & 15;
            id = kb_ids[b * 64 + w];
        }
        ids[tid] = id;
    }
    __syncthreads();
    for (int i = tid; i < 64 * 32; i += 256) {
        int row = i >> 5, q = i & 31;
        float4 v = reinterpret_cast<const float4*>(emb + (size_t)ids[row] * 128)[q];
        reinterpret_cast<float4*>(As + row * 128)[q] = v;
    }

    const float* W = dir ? Wr : Wf;
    const float* bias = dir ? br : bf;
    int tx = tid & 15, ty = tid >> 4;
    float acc[4][4] = {};

    for (int kc = 0; kc < 4; ++kc) {
        __syncthreads();
        for (int i = tid; i < 2048; i += 256) {
            int kk = i >> 6, cc = i & 63;
            Wsm[i] = W[(size_t)(kc * 32 + kk) * C + c0 + cc];
        }
        __syncthreads();
        #pragma unroll 8
        for (int kk = 0; kk < 32; ++kk) {
            float a0 = As[(ty * 4 + 0) * 128 + kc * 32 + kk];
            float a1 = As[(ty * 4 + 1) * 128 + kc * 32 + kk];
            float a2 = As[(ty * 4 + 2) * 128 + kc * 32 + kk];
            float a3 = As[(ty * 4 + 3) * 128 + kc * 32 + kk];
            float w0 = Wsm[kk * 64 + tx * 4 + 0];
            float w1 = Wsm[kk * 64 + tx * 4 + 1];
            float w2 = Wsm[kk * 64 + tx * 4 + 2];
            float w3 = Wsm[kk * 64 + tx * 4 + 3];
            acc[0][0] = fmaf(a0, w0, acc[0][0]); acc[0][1] = fmaf(a0, w1, acc[0][1]);
            acc[0][2] = fmaf(a0, w2, acc[0][2]); acc[0][3] = fmaf(a0, w3, acc[0][3]);
            acc[1][0] = fmaf(a1, w0, acc[1][0]); acc[1][1] = fmaf(a1, w1, acc[1][1]);
            acc[1][2] = fmaf(a1, w2, acc[1][2]); acc[1][3] = fmaf(a1, w3, acc[1][3]);
            acc[2][0] = fmaf(a2, w0, acc[2][0]); acc[2][1] = fmaf(a2, w1, acc[2][1]);
            acc[2][2] = fmaf(a2, w2, acc[2][2]); acc[2][3] = fmaf(a2, w3, acc[2][3]);
            acc[3][0] = fmaf(a3, w0, acc[3][0]); acc[3][1] = fmaf(a3, w1, acc[3][1]);
            acc[3][2] = fmaf(a3, w2, acc[3][2]); acc[3][3] = fmaf(a3, w3, acc[3][3]);
        }
    }
    #pragma unroll
    for (int i = 0; i < 4; ++i) {
        int r = r0 + ty * 4 + i;
        #pragma unroll
        for (int j = 0; j < 4; ++j) {
            int c = c0 + tx * 4 + j;
            out[(size_t)r * C + c] = acc[i][j] + bias[c];
        }
    }
}

// ---------------- lattice scan: 4-CTA cluster per (b,dir), c-sliced gates ----------------
// Rank r owns output columns c = r*32 + j (j=0..31) of h/c state.
// smem (floats):
#define SM_WS   0        // Wch slice: [k 0..127][cl 0..127], cl=g*32+j -> global col g*128+r*32+j  (16384)
#define SM_WW   16384    // Wwh slice: [k][cl 0..95]                                                 (12288)
#define SM_WL   28672    // Wlc slice: [k][j 0..31]                                                  (4096)
#define SM_H    32768    // h_hist [t 0..128][128]                                                   (16512)
#define SM_C    49280    // c_hist slice [t 0..128][32]                                              (4128)
#define SM_PART 53408    // 256
#define SM_WV   53664    // 96 (+pad)
#define SM_CW   53792    // cw exchange double buffer 2*128
#define LAT_FLOATS 54048 // = 216192 bytes

__global__ void __cluster_dims__(4, 1, 1) __launch_bounds__(256, 1)
lattice_kernel(
    const int* __restrict__ word_begin, const int* __restrict__ word_len,
    const int* __restrict__ seq_len,
    const float* __restrict__ f_Wch, const float* __restrict__ f_Wwh, const float* __restrict__ f_Wlc,
    const float* __restrict__ r_Wch, const float* __restrict__ r_Wwh, const float* __restrict__ r_Wlc)
{
    extern __shared__ float sm[];
    float* Ws   = sm + SM_WS;
    float* Ww   = sm + SM_WW;
    float* Wl   = sm + SM_WL;
    float* hist = sm + SM_H;
    float* ch   = sm + SM_C;
    float* part = sm + SM_PART;
    float* wv   = sm + SM_WV;
    float* cwb  = sm + SM_CW;
    __shared__ int s_wbeg[64], s_wend[64];
    __shared__ unsigned s_m0, s_m1;
    __shared__ __align__(8) unsigned long long s_barh[2], s_barw[2];

    int tid  = threadIdx.x;
    int cta  = blockIdx.x;
    int sid  = cta >> 2, rank = cta & 3;
    int dir = sid >> 4, b = sid & 15;
    const float* Wch = dir ? r_Wch : f_Wch;
    const float* Wwh = dir ? r_Wwh : f_Wwh;
    const float* Wlc = dir ? r_Wlc : f_Wlc;
    const float* Xg  = g_Xg + (size_t)sid * 128 * 512;
    const float* Xl  = g_Xl + (size_t)sid * 128 * 128;
    const float* Wg  = g_Wg + (size_t)sid * 64 * 384;
    int Lb = seq_len[b];
    int cbase = rank * 32;

    // load permuted weight slices
    for (int i = tid; i < 16384; i += 256) {
        int k = i >> 7, cl = i & 127;
        Ws[i] = Wch[(size_t)k * 512 + (cl >> 5) * 128 + cbase + (cl & 31)];
    }
    for (int i = tid; i < 12288; i += 256) {
        int k = i / 96, cl = i % 96;
        Ww[i] = Wwh[(size_t)k * 384 + (cl >> 5) * 128 + cbase + (cl & 31)];
    }
    for (int i = tid; i < 4096; i += 256) {
        int k = i >> 5, j = i & 31;
        Wl[i] = Wlc[(size_t)k * 128 + cbase + j];
    }
    if (tid < 128) hist[tid] = 0.f;
    if (tid < 32)  ch[tid] = 0.f;
    if (tid == 0) {
        mbar_init(smem_u32(&s_barh[0]), 128);
        mbar_init(smem_u32(&s_barh[1]), 128);
        mbar_init(smem_u32(&s_barw[0]), 128);
        mbar_init(smem_u32(&s_barw[1]), 128);
    }
    if (tid < 64) {
        int bg = word_begin[b * 64 + tid];
        int ln = word_len[b * 64 + tid];
        int e = min(bg + ln, 127);
        int be, en;
        if (dir == 0) { be = bg; en = e; } else { be = 127 - e; en = 127 - bg; }
        s_wbeg[tid] = be;
        s_wend[tid] = (e < Lb) ? en : -1;
    }
    __syncthreads();
    cluster_sync_();

    unsigned bh0 = smem_u32(&s_barh[0]);
    unsigned bw0 = smem_u32(&s_barw[0]);
    int ecnt = 0;
    int kg = tid >> 7, cl = tid & 127;

    for (int t = 0; t < 128; ++t) {
        float xg0 = 0.f, xg1 = 0.f, xg2 = 0.f, xg3 = 0.f;
        if (tid < 32) {
            const float* xgp = Xg + (size_t)t * 512 + cbase + tid;
            xg0 = xgp[0]; xg1 = xgp[128]; xg2 = xgp[256]; xg3 = xgp[384];
        }
        if (tid < 64) {
            unsigned m = __ballot_sync(0xffffffffu, s_wend[tid] == t);
            if ((tid & 31) == 0) { if (tid < 32) s_m0 = m; else s_m1 = m; }
        }
        // ---- gate GEMV (smem): 2-way k split, 128 cols ----
        {
            const float* wp = Ws + kg * 8192 + cl;
            const float4* h4 = reinterpret_cast<const float4*>(hist + t * 128) + kg * 16;
            float a0 = 0.f, a1 = 0.f, a2 = 0.f, a3 = 0.f;
            #pragma unroll
            for (int q = 0; q < 16; ++q) {
                float4 hv = h4[q];
                const float* w = wp + q * 512;
                a0 = fmaf(hv.x, w[0],   a0);
                a1 = fmaf(hv.y, w[128], a1);
                a2 = fmaf(hv.z, w[256], a2);
                a3 = fmaf(hv.w, w[384], a3);
            }
            part[tid] = (a0 + a1) + (a2 + a3);
        }
        __syncthreads();
        unsigned m0 = s_m0, m1 = s_m1;
        int wcnt = __popc(m0) + __popc(m1);
        float gi = 0.f, gf = 0.f, go = 0.f, gg = 0.f;
        if (tid < 32) {
            gi = part[tid]      + part[128 + tid]      + xg0;
            gf = part[32 + tid] + part[160 + tid]      + xg1;
            go = part[64 + tid] + part[192 + tid]      + xg2;
            gg = part[96 + tid] + part[224 + tid]      + xg3;
        }
        float ew = 0.f, ewcw = 0.f;
        if (wcnt) {
            __syncthreads();   // protect gate partial reads before events reuse part[]
            while (m0 | m1) {
                int w;
                if (m0) { w = __ffs(m0) - 1; m0 &= m0 - 1; }
                else    { w = 32 + __ffs(m1) - 1; m1 &= m1 - 1; }
                int bg = s_wbeg[w];
                float wgval = 0.f, xlv = 0.f;
                if (tid < 96) wgval = Wg[(size_t)w * 384 + (tid >> 5) * 128 + cbase + (tid & 31)];
                if (tid < 32) xlv = Xl[(size_t)t * 128 + cbase + tid];
                // wvec slice GEMV: 96 cols, 2-way k split
                if (tid < 192) {
                    int kg2 = (tid >= 96) ? 1 : 0;
                    int cl2 = tid - kg2 * 96;
                    const float* wp2 = Ww + kg2 * 6144 + cl2;
                    const float4* h4b = reinterpret_cast<const float4*>(hist + bg * 128) + kg2 * 16;
                    float a0 = 0.f, a1 = 0.f, a2 = 0.f, a3 = 0.f;
                    #pragma unroll
                    for (int q = 0; q < 16; ++q) {
                        float4 hv = h4b[q];
                        const float* ww = wp2 + q * 384;
                        a0 = fmaf(hv.x, ww[0],   a0);
                        a1 = fmaf(hv.y, ww[96],  a1);
                        a2 = fmaf(hv.z, ww[192], a2);
                        a3 = fmaf(hv.w, ww[288], a3);
                    }
                    part[tid] = (a0 + a1) + (a2 + a3);
                }
                __syncthreads();
                if (tid < 96) wv[tid] = part[tid] + part[96 + tid] + wgval;
                __syncthreads();
                float cwv = 0.f;
                int eb = ecnt & 1;
                unsigned bwa = bw0 + (unsigned)(ecnt & 1) * 8;
                if (tid < 32) {
                    float wi  = sigm(wv[tid]);
                    float wf  = sigm(wv[32 + tid]);
                    float wg_ = tanhf(wv[64 + tid]);
                    cwv = wf * ch[bg * 32 + tid] + wi * wg_;
                    unsigned la = smem_u32(&cwb[eb * 128 + cbase + tid]);
                    cwb[eb * 128 + cbase + tid] = cwv;
                    #pragma unroll
                    for (int p = 0; p < 4; ++p) if (p != rank) st_peer_f32(la, p, cwv);
                    mbar_arrive_self(bwa);
                    #pragma unroll
                    for (int p = 0; p < 4; ++p) if (p != rank) mbar_arrive_peer(bwa, p);
                }
                mbar_wait(bwa, (unsigned)((ecnt >> 1) & 1));
                // lg slice GEMV: 32 cols, 4-way k split over 128 threads
                if (tid < 128) {
                    int kg3 = tid >> 5, j = tid & 31;
                    const float* wp3 = Wl + kg3 * 1024 + j;
                    const float* cwf = cwb + eb * 128 + kg3 * 32;
                    float a0 = 0.f, a1 = 0.f;
                    #pragma unroll
                    for (int q = 0; q < 16; ++q) {
                        a0 = fmaf(cwf[2 * q],     wp3[(2 * q) * 32],     a0);
                        a1 = fmaf(cwf[2 * q + 1], wp3[(2 * q + 1) * 32], a1);
                    }
                    part[tid] = a0 + a1;
                }
                __syncthreads();
                if (tid < 32) {
                    float s = part[tid] + part[32 + tid] + part[64 + tid] + part[96 + tid] + xlv;
                    float e = expf(sigm(s));
                    ew += e;
                    ewcw += e * cwv;
                }
                __syncthreads();
                ++ecnt;
            }
        }
        // ---- pointwise on slice + h push ----
        unsigned bha = bh0 + (unsigned)(t & 1) * 8;
        if (tid < 32) {
            float i_ = sigm(gi), f_ = sigm(gf), o_ = sigm(go), g_ = tanhf(gg);
            float cp = ch[t * 32 + tid];
            float hp = hist[t * 128 + cbase + tid];
            float ct;
            if (wcnt) { float ec = expf(i_); ct = (ec * g_ + ewcw) / (ec + ew); }
            else      ct = f_ * cp + i_ * g_;
            float ht = o_ * tanhf(ct);
            bool v = dir ? (t >= 128 - Lb) : (t < Lb);
            float hn = v ? ht : hp;
            float cn = v ? ct : cp;
            unsigned la = smem_u32(&hist[(t + 1) * 128 + cbase + tid]);
            hist[(t + 1) * 128 + cbase + tid] = hn;
            #pragma unroll
            for (int p = 0; p < 4; ++p) if (p != rank) st_peer_f32(la, p, hn);
            ch[(t + 1) * 32 + tid] = cn;
            int pos = dir ? 127 - t : t;
            g_feats[((size_t)b * 128 + pos) * 256 + dir * 128 + cbase + tid] = v ? ht : 0.f;
            mbar_arrive_self(bha);
            #pragma unroll
            for (int p = 0; p < 4; ++p) if (p != rank) mbar_arrive_peer(bha, p);
        }
        mbar_wait(bha, (unsigned)((t >> 1) & 1));
    }
    cluster_sync_();
}

// ---------------- dense projection: 16 rows per 256-thread block ----------------
__global__ void dense_kernel(const float* __restrict__ W, const float* __restrict__ bias)
{
    __shared__ float Wsm[8192];
    __shared__ float Fs[16 * 256];
    int tid = threadIdx.x;
    int row0 = blockIdx.x * 16;
    for (int i = tid; i < 8192; i += 256) Wsm[i] = W[i];
    for (int i = tid; i < 4096; i += 256) Fs[i] = g_feats[(size_t)row0 * 256 + i];
    __syncthreads();
    int l = tid & 31, rr = tid >> 5;   // rows rr and rr+8
    float a0 = bias[l], a1 = a0;
    const float* f0 = Fs + rr * 256;
    const float* f1 = Fs + (rr + 8) * 256;
    #pragma unroll 8
    for (int q = 0; q < 256; ++q) {
        float w = Wsm[q * 32 + l];
        a0 = fmaf(f0[q], w, a0);
        a1 = fmaf(f1[q], w, a1);
    }
    g_logits[(size_t)(row0 + rr) * 32 + l]     = a0;
    g_logits[(size_t)(row0 + rr + 8) * 32 + l] = a1;
}

// ---------------- CRF: exp(T) precompute turns MUFU loop into FFMA loop ----------------
__global__ void crf_kernel(const int* __restrict__ label, const int* __restrict__ seq_len,
                           const float* __restrict__ crf_T)
{
    int b = blockIdx.x, l = threadIdx.x;
    __shared__ float Ts[1024], Es[1024];
    for (int i = l; i < 1024; i += 32) { float v = crf_T[i]; Ts[i] = v; Es[i] = expf(v); }
    __syncwarp();
    int L = seq_len[b];
    const float* lg = g_logits + (size_t)b * 4096;
    float alpha = lg[l];
    for (int t = 1; t < 128; ++t) {
        float m = alpha;
        for (int o = 16; o; o >>= 1) m = fmaxf(m, __shfl_xor_sync(0xffffffffu, m, o));
        float a = expf(alpha - m);
        float S = 0.f;
        #pragma unroll
        for (int i = 0; i < 32; ++i) {
            float ai = __shfl_sync(0xffffffffu, a, i);
            S = fmaf(ai, Es[i * 32 + l], S);
        }
        float nv = m + logf(S) + lg[t * 32 + l];
        if (t < L) alpha = nv;
    }
    float m = alpha;
    for (int o = 16; o; o >>= 1) m = fmaxf(m, __shfl_xor_sync(0xffffffffu, m, o));
    float e = expf(alpha - m);
    for (int o = 16; o; o >>= 1) e += __shfl_xor_sync(0xffffffffu, e, o);
    float logZ = m + logf(e);
    float gsum = 0.f;
    for (int t = l; t < 128; t += 32) {
        if (t < L) {
            int lab = label[b * 128 + t];
            gsum += lg[t * 32 + lab];
            if (t >= 1) gsum += Ts[label[b * 128 + t - 1] * 32 + lab];
        }
    }
    for (int o = 16; o; o >>= 1) gsum += __shfl_xor_sync(0xffffffffu, gsum, o);
    if (l == 0) g_res[b] = logZ - gsum;
}

__global__ void finalize_kernel(float* out)
{
    float s = 0.f;
    #pragma unroll
    for (int b = 0; b < 16; ++b) s += g_res[b];
    out[0] = s * 0.0625f;
}

// ---------------- launch ----------------
extern "C" void kernel_launch(void* const* d_in, const int* in_sizes, int n_in,
                              void* d_out, int out_size)
{
    const int*   char_ids    = (const int*)d_in[0];
    const int*   kb_word_ids = (const int*)d_in[1];
    const int*   word_begin  = (const int*)d_in[2];
    const int*   word_len    = (const int*)d_in[3];
    const int*   label       = (const int*)d_in[4];
    const int*   seq_len     = (const int*)d_in[5];
    const float* char_emb    = (const float*)d_in[6];
    const float* kb_emb      = (const float*)d_in[7];
    const float* dense_W     = (const float*)d_in[8];
    const float* dense_b     = (const float*)d_in[9];
    const float* crf_T       = (const float*)d_in[10];
    const float* f_Wcx = (const float*)d_in[11];
    const float* f_Wch = (const float*)d_in[12];
    const float* f_bc  = (const float*)d_in[13];
    const float* f_Wwx = (const float*)d_in[14];
    const float* f_Wwh = (const float*)d_in[15];
    const float* f_bw  = (const float*)d_in[16];
    const float* f_Wlx = (const float*)d_in[17];
    const float* f_Wlc = (const float*)d_in[18];
    const float* f_bl  = (const float*)d_in[19];
    const float* r_Wcx = (const float*)d_in[20];
    const float* r_Wch = (const float*)d_in[21];
    const float* r_bc  = (const float*)d_in[22];
    const float* r_Wwx = (const float*)d_in[23];
    const float* r_Wwh = (const float*)d_in[24];
    const float* r_bw  = (const float*)d_in[25];
    const float* r_Wlx = (const float*)d_in[26];
    const float* r_Wlc = (const float*)d_in[27];
    const float* r_bl  = (const float*)d_in[28];

    const int LAT_SMEM = LAT_FLOATS * 4;  // 216192 B
    cudaFuncSetAttribute(lattice_kernel, cudaFuncAttributeMaxDynamicSharedMemorySize, LAT_SMEM);

    gemm_gather_kernel<<<dim3(8, 64), 256>>>(0, char_ids, kb_word_ids, char_emb, kb_emb,
                                             f_Wcx, r_Wcx, f_bc, r_bc, 512, 2048);
    gemm_gather_kernel<<<dim3(2, 64), 256>>>(1, char_ids, kb_word_ids, char_emb, kb_emb,
                                             f_Wlx, r_Wlx, f_bl, r_bl, 128, 2048);
    gemm_gather_kernel<<<dim3(6, 32), 256>>>(2, char_ids, kb_word_ids, char_emb, kb_emb,
                                             f_Wwx, r_Wwx, f_bw, r_bw, 384, 1024);

    lattice_kernel<<<128, 256, LAT_SMEM>>>(word_begin, word_len, seq_len,
                                           f_Wch, f_Wwh, f_Wlc, r_Wch, r_Wwh, r_Wlc);

    dense_kernel<<<128, 256>>>(dense_W, dense_b);
    crf_kernel<<<16, 32>>>(label, seq_len, crf_T);
    finalize_kernel<<<1, 1>>>((float*)d_out);
}

// round 7
// speedup vs baseline: 1.0047x; 1.0047x over previous
#include <cuda_runtime.h>
#include <math.h>

// B=16, S=128, N=64, E=DK=H=128, L=32

// -------- device scratch --------
__device__ float g_Xg[2*16*128*512];   // X@Wcx+bc, scan order
__device__ float g_Xl[2*16*128*128];   // X@Wlx+bl
__device__ float g_Wg[2*16*64*384];    // Xw@Wwx+bw
__device__ float g_feats[16*128*256];
__device__ float g_logits[16*128*32];
__device__ float g_res[16];

__device__ __forceinline__ float sigm(float x) { return 1.f / (1.f + expf(-x)); }

__device__ __forceinline__ unsigned smem_u32(const void* p) {
    unsigned a;
    asm("{ .reg .u64 t; cvta.to.shared.u64 t, %1; cvt.u32.u64 %0, t; }" : "=r"(a) : "l"(p));
    return a;
}
__device__ __forceinline__ void st_peer_f32(unsigned a, int p, float v) {
    unsigned r;
    asm volatile("mapa.shared::cluster.u32 %0, %1, %2;" : "=r"(r) : "r"(a), "r"(p));
    asm volatile("st.shared::cluster.f32 [%0], %1;" :: "r"(r), "f"(v) : "memory");
}
__device__ __forceinline__ void mbar_init(unsigned a, unsigned c) {
    asm volatile("mbarrier.init.shared.b64 [%0], %1;" :: "r"(a), "r"(c) : "memory");
}
__device__ __forceinline__ void mbar_arrive_self(unsigned a) {
    asm volatile("mbarrier.arrive.release.cluster.shared::cta.b64 _, [%0];" :: "r"(a) : "memory");
}
__device__ __forceinline__ void mbar_arrive_peer(unsigned a, int p) {
    unsigned r;
    asm volatile("mapa.shared::cluster.u32 %0, %1, %2;" : "=r"(r) : "r"(a), "r"(p));
    asm volatile("mbarrier.arrive.release.cluster.shared::cluster.b64 _, [%0];" :: "r"(r) : "memory");
}
__device__ __forceinline__ void mbar_wait(unsigned a, unsigned parity) {
    asm volatile("{\n\t.reg .pred P;\n"
        "WL%=:\n\tmbarrier.try_wait.parity.acquire.cluster.shared::cta.b64 P, [%0], %1, 0x989680;\n"
        "\t@P bra WD%=;\n\tbra WL%=;\nWD%=:\n\t}" :: "r"(a), "r"(parity) : "memory");
}
__device__ __forceinline__ void cluster_sync_() {
    asm volatile("barrier.cluster.arrive.aligned;" ::: "memory");
    asm volatile("barrier.cluster.wait.aligned;" ::: "memory");
}

// ---------------- precompute GEMMs with embedding gather ----------------
__global__ void gemm_gather_kernel(int mode,
    const int* __restrict__ char_ids, const int* __restrict__ kb_ids,
    const float* __restrict__ char_emb, const float* __restrict__ kb_emb,
    const float* __restrict__ Wf, const float* __restrict__ Wr,
    const float* __restrict__ bf, const float* __restrict__ br,
    int C, int rows_per_dir)
{
    __shared__ float As[64 * 128];
    __shared__ float Wsm[32 * 64];
    __shared__ int ids[64];
    int tid = threadIdx.x;
    int c0 = blockIdx.x * 64;
    int r0 = blockIdx.y * 64;
    int dir = (r0 >= rows_per_dir) ? 1 : 0;

    float* out = (mode == 0) ? g_Xg : (mode == 1) ? g_Xl : g_Wg;
    const float* emb = (mode == 2) ? kb_emb : char_emb;

    if (tid < 64) {
        int r = r0 + tid;
        int id;
        if (mode < 2) {
            int t = r & 127, b = (r >> 7) & 15;
            int pos = dir ? (127 - t) : t;
            id = char_ids[b * 128 + pos];
        } else {
            int w = r & 63, b = (r >> 6) & 15;
            id = kb_ids[b * 64 + w];
        }
        ids[tid] = id;
    }
    __syncthreads();
    for (int i = tid; i < 64 * 32; i += 256) {
        int row = i >> 5, q = i & 31;
        float4 v = reinterpret_cast<const float4*>(emb + (size_t)ids[row] * 128)[q];
        reinterpret_cast<float4*>(As + row * 128)[q] = v;
    }

    const float* W = dir ? Wr : Wf;
    const float* bias = dir ? br : bf;
    int tx = tid & 15, ty = tid >> 4;
    float acc[4][4] = {};

    for (int kc = 0; kc < 4; ++kc) {
        __syncthreads();
        for (int i = tid; i < 2048; i += 256) {
            int kk = i >> 6, cc = i & 63;
            Wsm[i] = W[(size_t)(kc * 32 + kk) * C + c0 + cc];
        }
        __syncthreads();
        #pragma unroll 8
        for (int kk = 0; kk < 32; ++kk) {
            float a0 = As[(ty * 4 + 0) * 128 + kc * 32 + kk];
            float a1 = As[(ty * 4 + 1) * 128 + kc * 32 + kk];
            float a2 = As[(ty * 4 + 2) * 128 + kc * 32 + kk];
            float a3 = As[(ty * 4 + 3) * 128 + kc * 32 + kk];
            float w0 = Wsm[kk * 64 + tx * 4 + 0];
            float w1 = Wsm[kk * 64 + tx * 4 + 1];
            float w2 = Wsm[kk * 64 + tx * 4 + 2];
            float w3 = Wsm[kk * 64 + tx * 4 + 3];
            acc[0][0] = fmaf(a0, w0, acc[0][0]); acc[0][1] = fmaf(a0, w1, acc[0][1]);
            acc[0][2] = fmaf(a0, w2, acc[0][2]); acc[0][3] = fmaf(a0, w3, acc[0][3]);
            acc[1][0] = fmaf(a1, w0, acc[1][0]); acc[1][1] = fmaf(a1, w1, acc[1][1]);
            acc[1][2] = fmaf(a1, w2, acc[1][2]); acc[1][3] = fmaf(a1, w3, acc[1][3]);
            acc[2][0] = fmaf(a2, w0, acc[2][0]); acc[2][1] = fmaf(a2, w1, acc[2][1]);
            acc[2][2] = fmaf(a2, w2, acc[2][2]); acc[2][3] = fmaf(a2, w3, acc[2][3]);
            acc[3][0] = fmaf(a3, w0, acc[3][0]); acc[3][1] = fmaf(a3, w1, acc[3][1]);
            acc[3][2] = fmaf(a3, w2, acc[3][2]); acc[3][3] = fmaf(a3, w3, acc[3][3]);
        }
    }
    #pragma unroll
    for (int i = 0; i < 4; ++i) {
        int r = r0 + ty * 4 + i;
        #pragma unroll
        for (int j = 0; j < 4; ++j) {
            int c = c0 + tx * 4 + j;
            out[(size_t)r * C + c] = acc[i][j] + bias[c];
        }
    }
}

// ---------------- lattice scan: 4-CTA cluster per (b,dir), c-sliced gates ----------------
// Rank r owns output columns c = r*32 + j (j=0..31) of h/c state.
// smem (floats):
#define SM_WS   0        // Wch slice: [k 0..127][cl 0..127], cl=g*32+j -> global col g*128+r*32+j  (16384)
#define SM_WW   16384    // Wwh slice: [k][cl 0..95]                                                 (12288)
#define SM_WL   28672    // Wlc slice: [k][j 0..31]                                                  (4096)
#define SM_H    32768    // h_hist [t 0..128][128]                                                   (16512)
#define SM_C    49280    // c_hist slice [t 0..128][32]                                              (4128)
#define SM_PART 53408    // 256
#define SM_WV   53664    // 96 (+pad)
#define SM_CW   53792    // cw exchange double buffer 2*128
#define LAT_FLOATS 54048 // = 216192 bytes

__global__ void __cluster_dims__(4, 1, 1) __launch_bounds__(256, 1)
lattice_kernel(
    const int* __restrict__ word_begin, const int* __restrict__ word_len,
    const int* __restrict__ seq_len,
    const float* __restrict__ f_Wch, const float* __restrict__ f_Wwh, const float* __restrict__ f_Wlc,
    const float* __restrict__ r_Wch, const float* __restrict__ r_Wwh, const float* __restrict__ r_Wlc)
{
    extern __shared__ float sm[];
    float* Ws   = sm + SM_WS;
    float* Ww   = sm + SM_WW;
    float* Wl   = sm + SM_WL;
    float* hist = sm + SM_H;
    float* ch   = sm + SM_C;
    float* part = sm + SM_PART;
    float* wv   = sm + SM_WV;
    float* cwb  = sm + SM_CW;
    __shared__ int s_wbeg[64], s_wend[64];
    __shared__ unsigned s_m0, s_m1;
    __shared__ __align__(8) unsigned long long s_barh[2], s_barw[2];

    int tid  = threadIdx.x;
    int cta  = blockIdx.x;
    int sid  = cta >> 2, rank = cta & 3;
    int dir = sid >> 4, b = sid & 15;
    const float* Wch = dir ? r_Wch : f_Wch;
    const float* Wwh = dir ? r_Wwh : f_Wwh;
    const float* Wlc = dir ? r_Wlc : f_Wlc;
    const float* Xg  = g_Xg + (size_t)sid * 128 * 512;
    const float* Xl  = g_Xl + (size_t)sid * 128 * 128;
    const float* Wg  = g_Wg + (size_t)sid * 64 * 384;
    int Lb = seq_len[b];
    int cbase = rank * 32;

    // load permuted weight slices
    for (int i = tid; i < 16384; i += 256) {
        int k = i >> 7, cl = i & 127;
        Ws[i] = Wch[(size_t)k * 512 + (cl >> 5) * 128 + cbase + (cl & 31)];
    }
    for (int i = tid; i < 12288; i += 256) {
        int k = i / 96, cl = i % 96;
        Ww[i] = Wwh[(size_t)k * 384 + (cl >> 5) * 128 + cbase + (cl & 31)];
    }
    for (int i = tid; i < 4096; i += 256) {
        int k = i >> 5, j = i & 31;
        Wl[i] = Wlc[(size_t)k * 128 + cbase + j];
    }
    if (tid < 128) hist[tid] = 0.f;
    if (tid < 32)  ch[tid] = 0.f;
    if (tid == 0) {
        mbar_init(smem_u32(&s_barh[0]), 128);
        mbar_init(smem_u32(&s_barh[1]), 128);
        mbar_init(smem_u32(&s_barw[0]), 128);
        mbar_init(smem_u32(&s_barw[1]), 128);
    }
    if (tid < 64) {
        int bg = word_begin[b * 64 + tid];
        int ln = word_len[b * 64 + tid];
        int e = min(bg + ln, 127);
        int be, en;
        if (dir == 0) { be = bg; en = e; } else { be = 127 - e; en = 127 - bg; }
        s_wbeg[tid] = be;
        s_wend[tid] = (e < Lb) ? en : -1;
    }
    __syncthreads();
    cluster_sync_();

    unsigned bh0 = smem_u32(&s_barh[0]);
    unsigned bw0 = smem_u32(&s_barw[0]);
    int ecnt = 0;
    int kg = tid >> 7, cl = tid & 127;

    for (int t = 0; t < 128; ++t) {
        float xg0 = 0.f, xg1 = 0.f, xg2 = 0.f, xg3 = 0.f;
        if (tid < 32) {
            const float* xgp = Xg + (size_t)t * 512 + cbase + tid;
            xg0 = xgp[0]; xg1 = xgp[128]; xg2 = xgp[256]; xg3 = xgp[384];
        }
        if (tid < 64) {
            unsigned m = __ballot_sync(0xffffffffu, s_wend[tid] == t);
            if ((tid & 31) == 0) { if (tid < 32) s_m0 = m; else s_m1 = m; }
        }
        // ---- gate GEMV (smem): 2-way k split, 128 cols ----
        {
            const float* wp = Ws + kg * 8192 + cl;
            const float4* h4 = reinterpret_cast<const float4*>(hist + t * 128) + kg * 16;
            float a0 = 0.f, a1 = 0.f, a2 = 0.f, a3 = 0.f;
            #pragma unroll
            for (int q = 0; q < 16; ++q) {
                float4 hv = h4[q];
                const float* w = wp + q * 512;
                a0 = fmaf(hv.x, w[0],   a0);
                a1 = fmaf(hv.y, w[128], a1);
                a2 = fmaf(hv.z, w[256], a2);
                a3 = fmaf(hv.w, w[384], a3);
            }
            part[tid] = (a0 + a1) + (a2 + a3);
        }
        __syncthreads();
        unsigned m0 = s_m0, m1 = s_m1;
        int wcnt = __popc(m0) + __popc(m1);
        float gi = 0.f, gf = 0.f, go = 0.f, gg = 0.f;
        if (tid < 32) {
            gi = part[tid]      + part[128 + tid]      + xg0;
            gf = part[32 + tid] + part[160 + tid]      + xg1;
            go = part[64 + tid] + part[192 + tid]      + xg2;
            gg = part[96 + tid] + part[224 + tid]      + xg3;
        }
        float ew = 0.f, ewcw = 0.f;
        if (wcnt) {
            __syncthreads();   // protect gate partial reads before events reuse part[]
            while (m0 | m1) {
                int w;
                if (m0) { w = __ffs(m0) - 1; m0 &= m0 - 1; }
                else    { w = 32 + __ffs(m1) - 1; m1 &= m1 - 1; }
                int bg = s_wbeg[w];
                float wgval = 0.f, xlv = 0.f;
                if (tid < 96) wgval = Wg[(size_t)w * 384 + (tid >> 5) * 128 + cbase + (tid & 31)];
                if (tid < 32) xlv = Xl[(size_t)t * 128 + cbase + tid];
                // wvec slice GEMV: 96 cols, 2-way k split
                if (tid < 192) {
                    int kg2 = (tid >= 96) ? 1 : 0;
                    int cl2 = tid - kg2 * 96;
                    const float* wp2 = Ww + kg2 * 6144 + cl2;
                    const float4* h4b = reinterpret_cast<const float4*>(hist + bg * 128) + kg2 * 16;
                    float a0 = 0.f, a1 = 0.f, a2 = 0.f, a3 = 0.f;
                    #pragma unroll
                    for (int q = 0; q < 16; ++q) {
                        float4 hv = h4b[q];
                        const float* ww = wp2 + q * 384;
                        a0 = fmaf(hv.x, ww[0],   a0);
                        a1 = fmaf(hv.y, ww[96],  a1);
                        a2 = fmaf(hv.z, ww[192], a2);
                        a3 = fmaf(hv.w, ww[288], a3);
                    }
                    part[tid] = (a0 + a1) + (a2 + a3);
                }
                __syncthreads();
                if (tid < 96) wv[tid] = part[tid] + part[96 + tid] + wgval;
                __syncthreads();
                float cwv = 0.f;
                int eb = ecnt & 1;
                unsigned bwa = bw0 + (unsigned)(ecnt & 1) * 8;
                if (tid < 32) {
                    float wi  = sigm(wv[tid]);
                    float wf  = sigm(wv[32 + tid]);
                    float wg_ = tanhf(wv[64 + tid]);
                    cwv = wf * ch[bg * 32 + tid] + wi * wg_;
                    unsigned la = smem_u32(&cwb[eb * 128 + cbase + tid]);
                    cwb[eb * 128 + cbase + tid] = cwv;
                    #pragma unroll
                    for (int p = 0; p < 4; ++p) if (p != rank) st_peer_f32(la, p, cwv);
                    mbar_arrive_self(bwa);
                    #pragma unroll
                    for (int p = 0; p < 4; ++p) if (p != rank) mbar_arrive_peer(bwa, p);
                }
                mbar_wait(bwa, (unsigned)((ecnt >> 1) & 1));
                // lg slice GEMV: 32 cols, 4-way k split over 128 threads
                if (tid < 128) {
                    int kg3 = tid >> 5, j = tid & 31;
                    const float* wp3 = Wl + kg3 * 1024 + j;
                    const float* cwf = cwb + eb * 128 + kg3 * 32;
                    float a0 = 0.f, a1 = 0.f;
                    #pragma unroll
                    for (int q = 0; q < 16; ++q) {
                        a0 = fmaf(cwf[2 * q],     wp3[(2 * q) * 32],     a0);
                        a1 = fmaf(cwf[2 * q + 1], wp3[(2 * q + 1) * 32], a1);
                    }
                    part[tid] = a0 + a1;
                }
                __syncthreads();
                if (tid < 32) {
                    float s = part[tid] + part[32 + tid] + part[64 + tid] + part[96 + tid] + xlv;
                    float e = expf(sigm(s));
                    ew += e;
                    ewcw += e * cwv;
                }
                __syncthreads();
                ++ecnt;
            }
        }
        // ---- pointwise on slice + h push ----
        unsigned bha = bh0 + (unsigned)(t & 1) * 8;
        if (tid < 32) {
            float i_ = sigm(gi), f_ = sigm(gf), o_ = sigm(go), g_ = tanhf(gg);
            float cp = ch[t * 32 + tid];
            float hp = hist[t * 128 + cbase + tid];
            float ct;
            if (wcnt) { float ec = expf(i_); ct = (ec * g_ + ewcw) / (ec + ew); }
            else      ct = f_ * cp + i_ * g_;
            float ht = o_ * tanhf(ct);
            bool v = dir ? (t >= 128 - Lb) : (t < Lb);
            float hn = v ? ht : hp;
            float cn = v ? ct : cp;
            unsigned la = smem_u32(&hist[(t + 1) * 128 + cbase + tid]);
            hist[(t + 1) * 128 + cbase + tid] = hn;
            #pragma unroll
            for (int p = 0; p < 4; ++p) if (p != rank) st_peer_f32(la, p, hn);
            ch[(t + 1) * 32 + tid] = cn;
            int pos = dir ? 127 - t : t;
            g_feats[((size_t)b * 128 + pos) * 256 + dir * 128 + cbase + tid] = v ? ht : 0.f;
            mbar_arrive_self(bha);
            #pragma unroll
            for (int p = 0; p < 4; ++p) if (p != rank) mbar_arrive_peer(bha, p);
        }
        mbar_wait(bha, (unsigned)((t >> 1) & 1));
    }
    cluster_sync_();
}

// ---------------- dense projection: 16 rows per 256-thread block ----------------
__global__ void dense_kernel(const float* __restrict__ W, const float* __restrict__ bias)
{
    __shared__ float Wsm[8192];
    __shared__ float Fs[16 * 256];
    int tid = threadIdx.x;
    int row0 = blockIdx.x * 16;
    for (int i = tid; i < 8192; i += 256) Wsm[i] = W[i];
    for (int i = tid; i < 4096; i += 256) Fs[i] = g_feats[(size_t)row0 * 256 + i];
    __syncthreads();
    int l = tid & 31, rr = tid >> 5;   // rows rr and rr+8
    float a0 = bias[l], a1 = a0;
    const float* f0 = Fs + rr * 256;
    const float* f1 = Fs + (rr + 8) * 256;
    #pragma unroll 8
    for (int q = 0; q < 256; ++q) {
        float w = Wsm[q * 32 + l];
        a0 = fmaf(f0[q], w, a0);
        a1 = fmaf(f1[q], w, a1);
    }
    g_logits[(size_t)(row0 + rr) * 32 + l]     = a0;
    g_logits[(size_t)(row0 + rr + 8) * 32 + l] = a1;
}

// ---------------- CRF: exp(T) precompute turns MUFU loop into FFMA loop ----------------
__global__ void crf_kernel(const int* __restrict__ label, const int* __restrict__ seq_len,
                           const float* __restrict__ crf_T)
{
    int b = blockIdx.x, l = threadIdx.x;
    __shared__ float Ts[1024], Es[1024];
    for (int i = l; i < 1024; i += 32) { float v = crf_T[i]; Ts[i] = v; Es[i] = expf(v); }
    __syncwarp();
    int L = seq_len[b];
    const float* lg = g_logits + (size_t)b * 4096;
    float alpha = lg[l];
    for (int t = 1; t < 128; ++t) {
        float m = alpha;
        for (int o = 16; o; o >>= 1) m = fmaxf(m, __shfl_xor_sync(0xffffffffu, m, o));
        float a = expf(alpha - m);
        float S = 0.f;
        #pragma unroll
        for (int i = 0; i < 32; ++i) {
            float ai = __shfl_sync(0xffffffffu, a, i);
            S = fmaf(ai, Es[i * 32 + l], S);
        }
        float nv = m + logf(S) + lg[t * 32 + l];
        if (t < L) alpha = nv;
    }
    float m = alpha;
    for (int o = 16; o; o >>= 1) m = fmaxf(m, __shfl_xor_sync(0xffffffffu, m, o));
    float e = expf(alpha - m);
    for (int o = 16; o; o >>= 1) e += __shfl_xor_sync(0xffffffffu, e, o);
    float logZ = m + logf(e);
    float gsum = 0.f;
    for (int t = l; t < 128; t += 32) {
        if (t < L) {
            int lab = label[b * 128 + t];
            gsum += lg[t * 32 + lab];
            if (t >= 1) gsum += Ts[label[b * 128 + t - 1] * 32 + lab];
        }
    }
    for (int o = 16; o; o >>= 1) gsum += __shfl_xor_sync(0xffffffffu, gsum, o);
    if (l == 0) g_res[b] = logZ - gsum;
}

__global__ void finalize_kernel(float* out)
{
    float s = 0.f;
    #pragma unroll
    for (int b = 0; b < 16; ++b) s += g_res[b];
    out[0] = s * 0.0625f;
}

// ---------------- launch ----------------
extern "C" void kernel_launch(void* const* d_in, const int* in_sizes, int n_in,
                              void* d_out, int out_size)
{
    const int*   char_ids    = (const int*)d_in[0];
    const int*   kb_word_ids = (const int*)d_in[1];
    const int*   word_begin  = (const int*)d_in[2];
    const int*   word_len    = (const int*)d_in[3];
    const int*   label       = (const int*)d_in[4];
    const int*   seq_len     = (const int*)d_in[5];
    const float* char_emb    = (const float*)d_in[6];
    const float* kb_emb      = (const float*)d_in[7];
    const float* dense_W     = (const float*)d_in[8];
    const float* dense_b     = (const float*)d_in[9];
    const float* crf_T       = (const float*)d_in[10];
    const float* f_Wcx = (const float*)d_in[11];
    const float* f_Wch = (const float*)d_in[12];
    const float* f_bc  = (const float*)d_in[13];
    const float* f_Wwx = (const float*)d_in[14];
    const float* f_Wwh = (const float*)d_in[15];
    const float* f_bw  = (const float*)d_in[16];
    const float* f_Wlx = (const float*)d_in[17];
    const float* f_Wlc = (const float*)d_in[18];
    const float* f_bl  = (const float*)d_in[19];
    const float* r_Wcx = (const float*)d_in[20];
    const float* r_Wch = (const float*)d_in[21];
    const float* r_bc  = (const float*)d_in[22];
    const float* r_Wwx = (const float*)d_in[23];
    const float* r_Wwh = (const float*)d_in[24];
    const float* r_bw  = (const float*)d_in[25];
    const float* r_Wlx = (const float*)d_in[26];
    const float* r_Wlc = (const float*)d_in[27];
    const float* r_bl  = (const float*)d_in[28];

    const int LAT_SMEM = LAT_FLOATS * 4;  // 216192 B
    cudaFuncSetAttribute(lattice_kernel, cudaFuncAttributeMaxDynamicSharedMemorySize, LAT_SMEM);

    gemm_gather_kernel<<<dim3(8, 64), 256>>>(0, char_ids, kb_word_ids, char_emb, kb_emb,
                                             f_Wcx, r_Wcx, f_bc, r_bc, 512, 2048);
    gemm_gather_kernel<<<dim3(2, 64), 256>>>(1, char_ids, kb_word_ids, char_emb, kb_emb,
                                             f_Wlx, r_Wlx, f_bl, r_bl, 128, 2048);
    gemm_gather_kernel<<<dim3(6, 32), 256>>>(2, char_ids, kb_word_ids, char_emb, kb_emb,
                                             f_Wwx, r_Wwx, f_bw, r_bw, 384, 1024);

    lattice_kernel<<<128, 256, LAT_SMEM>>>(word_begin, word_len, seq_len,
                                           f_Wch, f_Wwh, f_Wlc, r_Wch, r_Wwh, r_Wlc);

    dense_kernel<<<128, 256>>>(dense_W, dense_b);
    crf_kernel<<<16, 32>>>(label, seq_len, crf_T);
    finalize_kernel<<<1, 1>>>((float*)d_out);
}